// round 9
// baseline (speedup 1.0000x reference)
#include <cuda_runtime.h>
#include <cuda_bf16.h>
#include <cstdint>

// ---------------------------------------------------------------------------
// RWKV Tmix x060 block.  B=4, T=2048, C=2048, H=32, HS=64.
// Round 9 (= round 7 resubmit; broker timeouts in rounds 7 and 8):
// (a) big GEMMs on 256x128 block tiles (fewer load ops per flop);
// (b) WKV scan split 4-way over state columns (512 blocks, float4 LDS).
// ---------------------------------------------------------------------------

#define B_  4
#define T_  2048
#define C_  2048
#define H_  32
#define MT_ (B_*T_)                       // 8192 rows
#define MTC_ ((size_t)MT_*(size_t)C_)     // 16777216 elements

__device__ __align__(128) float g_scratch[15ull*16777216ull + 4ull*1048576ull];

#define OFF_X    (0ull*16777216ull)
#define OFF_MIX0 (1ull*16777216ull)
#define OFF_MIX1 (2ull*16777216ull)
#define OFF_MIX2 (3ull*16777216ull)
#define OFF_MIX3 (4ull*16777216ull)
#define OFF_MW   (5ull*16777216ull)
#define OFF_W    (7ull*16777216ull)
#define OFF_R    (8ull*16777216ull)
#define OFF_K    (9ull*16777216ull)
#define OFF_V    (10ull*16777216ull)
#define OFF_V2   (11ull*16777216ull)
#define OFF_DEC  (12ull*16777216ull)
#define OFF_Y    (13ull*16777216ull)

// bf16 buffers
#define MEG 1048576ull
__device__ __align__(128) __nv_bfloat16 g_bf16[120ull*MEG];
#define BF_XH   (0ull*MEG)
#define BF_XL   (16ull*MEG)
#define BF_YH   (32ull*MEG)
#define BF_YL   (48ull*MEG)
#define BF_VWH  (64ull*MEG)
#define BF_VWL  (68ull*MEG)
#define BF_OWH  (72ull*MEG)
#define BF_OWL  (76ull*MEG)
#define BF_GXBF (80ull*MEG)      // x in bf16 (epilogue of GEMM 1)
#define BF_XWBF (96ull*MEG)      // xw in bf16
#define BF_XXX  (112ull*MEG)     // xxx [8192,128]
#define BF_H32  (114ull*MEG)     // h32 padded [8192,128]
#define BF_H128 (116ull*MEG)     // h128 [8192,128]
#define BF_W1T  (118ull*MEG)                 // [128,2048]
#define BF_WW1T (118ull*MEG +  262144ull)    // [128,2048] (rows>=32 zero)
#define BF_DW1T (118ull*MEG +  524288ull)    // [128,2048]
#define BF_W2T  (118ull*MEG +  786432ull)    // [4][2048,32]
#define BF_WW2T (118ull*MEG + 1048576ull)    // [2048,32]
#define BF_DW2T (118ull*MEG + 1114112ull)    // [2048,128]

// ======================== mma.sync helpers =================================
__device__ __forceinline__ uint32_t smem_u32(const void* p) {
    uint32_t a;
    asm("{ .reg .u64 t; cvta.to.shared.u64 t, %1; cvt.u32.u64 %0, t; }" : "=r"(a) : "l"(p));
    return a;
}

__device__ __forceinline__ void mma16816(float* d, const uint32_t* a, const uint32_t* b) {
    asm volatile(
        "mma.sync.aligned.m16n8k16.row.col.f32.bf16.bf16.f32 "
        "{%0,%1,%2,%3}, {%4,%5,%6,%7}, {%8,%9}, {%0,%1,%2,%3};"
        : "+f"(d[0]), "+f"(d[1]), "+f"(d[2]), "+f"(d[3])
        : "r"(a[0]), "r"(a[1]), "r"(a[2]), "r"(a[3]), "r"(b[0]), "r"(b[1]));
}

__device__ __forceinline__ void ldsm4(uint32_t* r, uint32_t addr) {
    asm volatile("ldmatrix.sync.aligned.m8n8.x4.shared.b16 {%0,%1,%2,%3}, [%4];"
        : "=r"(r[0]), "=r"(r[1]), "=r"(r[2]), "=r"(r[3]) : "r"(addr));
}

__device__ __forceinline__ void cp16(uint32_t dst, const void* src) {
    asm volatile("cp.async.cg.shared.global [%0], [%1], 16;" :: "r"(dst), "l"(src));
}
#define CP_COMMIT() asm volatile("cp.async.commit_group;" ::: "memory")
#define CP_WAIT(n)  asm volatile("cp.async.wait_group %0;" :: "n"(n) : "memory")

// ---------------------------------------------------------------------------
// Split-bf16 mma.sync GEMM:  C[8192,2048] = A @ B^T   (hi/lo 3-term)
// Block tile 256x128, BK=32, 8 warps (warp 64x64), cp.async double buffer.
// Stage layout (80B pitch rows): A_hi[256] A_lo[256] B_hi[128] B_lo[128].
// ---------------------------------------------------------------------------
#define GM_AH  0u
#define GM_AL  20480u
#define GM_BH  40960u
#define GM_BL  51200u
#define GM_STG 61440u
#define GM_SMEM 122880

__global__ void __launch_bounds__(256, 1) gemm_mma(
    const __nv_bfloat16* __restrict__ a_hi, const __nv_bfloat16* __restrict__ a_lo,
    const __nv_bfloat16* __restrict__ b_hi, const __nv_bfloat16* __restrict__ b_lo,
    float* __restrict__ Cm, __nv_bfloat16* __restrict__ Cbf)
{
    extern __shared__ char smem[];
    const uint32_t sbase = smem_u32(smem);

    const int tid    = threadIdx.x;
    const int lane   = tid & 31;
    const int wid    = tid >> 5;
    const int warp_m = wid & 3;          // 4 warps over M (64 rows each)
    const int warp_n = wid >> 2;         // 2 warps over N (64 cols each)
    const int row0   = blockIdx.y * 256;
    const int col0   = blockIdx.x * 128;

    const __nv_bfloat16* sA0 = a_hi + (size_t)row0 * 2048;
    const __nv_bfloat16* sA1 = a_lo + (size_t)row0 * 2048;
    const __nv_bfloat16* sB0 = b_hi + (size_t)col0 * 2048;
    const __nv_bfloat16* sB1 = b_lo + (size_t)col0 * 2048;

    const int rrb = tid >> 2;            // base row (0..63)
    const int qd  = tid & 3;             // quad
    const int cc  = qd * 8;              // bf16 col offset

    auto issue = [&](int ch, int buf) {
        const uint32_t bb = sbase + (uint32_t)buf * GM_STG;
        const int kel = ch * 32;
#pragma unroll
        for (int s = 0; s < 4; s++) {
            int rr = rrb + s * 64;
            cp16(bb + GM_AH + (uint32_t)rr*80u + (uint32_t)qd*16u,
                 sA0 + (size_t)rr*2048 + kel + cc);
            cp16(bb + GM_AL + (uint32_t)rr*80u + (uint32_t)qd*16u,
                 sA1 + (size_t)rr*2048 + kel + cc);
        }
#pragma unroll
        for (int s = 0; s < 2; s++) {
            int rr = rrb + s * 64;
            cp16(bb + GM_BH + (uint32_t)rr*80u + (uint32_t)qd*16u,
                 sB0 + (size_t)rr*2048 + kel + cc);
            cp16(bb + GM_BL + (uint32_t)rr*80u + (uint32_t)qd*16u,
                 sB1 + (size_t)rr*2048 + kel + cc);
        }
        CP_COMMIT();
    };

    float acc[4][8][4];
#pragma unroll
    for (int i = 0; i < 4; i++)
#pragma unroll
        for (int j = 0; j < 8; j++)
#pragma unroll
            for (int q = 0; q < 4; q++) acc[i][j][q] = 0.f;

    issue(0, 0);

    const uint32_t lrow  = (uint32_t)(lane & 15);
    const uint32_t khalf = (uint32_t)((lane >> 4) << 3);

    for (int ch = 0; ch < 64; ch++) {
        if (ch < 63) { issue(ch + 1, (ch + 1) & 1); CP_WAIT(1); }
        else         { CP_WAIT(0); }
        __syncthreads();

        const uint32_t bb = sbase + (uint32_t)(ch & 1) * GM_STG;
        const uint32_t aH = bb + GM_AH;
        const uint32_t aL = bb + GM_AL;
        const uint32_t bH = bb + GM_BH;
        const uint32_t bL = bb + GM_BL;

#pragma unroll
        for (int k16 = 0; k16 < 32; k16 += 16) {
            const uint32_t kb = ((uint32_t)k16 + khalf) * 2u;
            uint32_t af[4][4], bf[8][2], bl[8][2];

#pragma unroll
            for (int f = 0; f < 4; f++)
                ldsm4(af[f], aH + (uint32_t)(warp_m*64 + f*16 + lrow)*80u + kb);
#pragma unroll
            for (int pr = 0; pr < 4; pr++) {
                uint32_t r[4];
                ldsm4(r, bH + (uint32_t)(warp_n*64 + pr*16 + lrow)*80u + kb);
                bf[2*pr+0][0] = r[0]; bf[2*pr+0][1] = r[2];
                bf[2*pr+1][0] = r[1]; bf[2*pr+1][1] = r[3];
            }
#pragma unroll
            for (int pr = 0; pr < 4; pr++) {
                uint32_t r[4];
                ldsm4(r, bL + (uint32_t)(warp_n*64 + pr*16 + lrow)*80u + kb);
                bl[2*pr+0][0] = r[0]; bl[2*pr+0][1] = r[2];
                bl[2*pr+1][0] = r[1]; bl[2*pr+1][1] = r[3];
            }
            // hh + hl
#pragma unroll
            for (int mf = 0; mf < 4; mf++)
#pragma unroll
                for (int nf = 0; nf < 8; nf++) {
                    mma16816(acc[mf][nf], af[mf], bf[nf]);
                    mma16816(acc[mf][nf], af[mf], bl[nf]);
                }
            // lh (reuse af regs for A_lo)
#pragma unroll
            for (int f = 0; f < 4; f++)
                ldsm4(af[f], aL + (uint32_t)(warp_m*64 + f*16 + lrow)*80u + kb);
#pragma unroll
            for (int mf = 0; mf < 4; mf++)
#pragma unroll
                for (int nf = 0; nf < 8; nf++)
                    mma16816(acc[mf][nf], af[mf], bf[nf]);
        }
        __syncthreads();
    }

    const int erow = row0 + warp_m*64 + (lane >> 2);
    const int ecol = col0 + warp_n*64 + (lane & 3)*2;
#pragma unroll
    for (int mf = 0; mf < 4; mf++) {
#pragma unroll
        for (int nf = 0; nf < 8; nf++) {
            float* p0 = Cm + (size_t)(erow + mf*16    )*2048 + ecol + nf*8;
            float* p1 = Cm + (size_t)(erow + mf*16 + 8)*2048 + ecol + nf*8;
            *(float2*)p0 = make_float2(acc[mf][nf][0], acc[mf][nf][1]);
            *(float2*)p1 = make_float2(acc[mf][nf][2], acc[mf][nf][3]);
            if (Cbf) {
                __nv_bfloat162* q0 = (__nv_bfloat162*)(Cbf + (size_t)(erow + mf*16    )*2048 + ecol + nf*8);
                __nv_bfloat162* q1 = (__nv_bfloat162*)(Cbf + (size_t)(erow + mf*16 + 8)*2048 + ecol + nf*8);
                *q0 = __floats2bfloat162_rn(acc[mf][nf][0], acc[mf][nf][1]);
                *q1 = __floats2bfloat162_rn(acc[mf][nf][2], acc[mf][nf][3]);
            }
        }
    }
}

// ---------------------------------------------------------------------------
// Skinny GEMM:  C[8192,128] (bf16) = tanh( A[8192,2048] @ Bt[128,2048]^T )
// ---------------------------------------------------------------------------
#define GS_A_B   5120u
#define GS_BUF_B 15360u

__global__ void __launch_bounds__(256) gemm_skinny(
    const __nv_bfloat16* __restrict__ A,
    const __nv_bfloat16* __restrict__ Bt,
    __nv_bfloat16* __restrict__ C)
{
    __shared__ char smem[2*15360];
    const uint32_t sbase = smem_u32(smem);

    const int tid    = threadIdx.x;
    const int lane   = tid & 31;
    const int wid    = tid >> 5;
    const int warp_m = wid & 1;
    const int warp_n = wid >> 1;
    const int row0   = blockIdx.x * 64;

    const __nv_bfloat16* Ab = A + (size_t)row0 * 2048;

    auto issue = [&](int ch, int buf) {
        const uint32_t bb = sbase + (uint32_t)buf * GS_BUF_B;
        const int kel = ch * 32;
        cp16(bb + (uint32_t)(tid>>2)*80u + (uint32_t)(tid&3)*16u,
             Ab + (size_t)(tid>>2)*2048 + kel + (tid&3)*8);
#pragma unroll
        for (int s = 0; s < 2; s++) {
            int idx = tid + s*256;
            cp16(bb + GS_A_B + (uint32_t)(idx>>2)*80u + (uint32_t)(idx&3)*16u,
                 Bt + (size_t)(idx>>2)*2048 + kel + (idx&3)*8);
        }
        CP_COMMIT();
    };

    float acc[2][4][4];
#pragma unroll
    for (int i = 0; i < 2; i++)
#pragma unroll
        for (int j = 0; j < 4; j++)
#pragma unroll
            for (int q = 0; q < 4; q++) acc[i][j][q] = 0.f;

    issue(0, 0);

    const uint32_t lrow  = (uint32_t)(lane & 15);
    const uint32_t khalf = (uint32_t)((lane >> 4) << 3);

    for (int ch = 0; ch < 64; ch++) {
        if (ch < 63) { issue(ch + 1, (ch + 1) & 1); CP_WAIT(1); }
        else         { CP_WAIT(0); }
        __syncthreads();

        const uint32_t aB = sbase + (uint32_t)(ch & 1) * GS_BUF_B;
        const uint32_t bB = aB + GS_A_B;

#pragma unroll
        for (int k16 = 0; k16 < 32; k16 += 16) {
            const uint32_t kb = ((uint32_t)k16 + khalf) * 2u;
            uint32_t af[2][4], bfr[4][2];
#pragma unroll
            for (int f = 0; f < 2; f++)
                ldsm4(af[f], aB + (uint32_t)(warp_m*32 + f*16 + lrow)*80u + kb);
#pragma unroll
            for (int pr = 0; pr < 2; pr++) {
                uint32_t r[4];
                ldsm4(r, bB + (uint32_t)(warp_n*32 + pr*16 + lrow)*80u + kb);
                bfr[2*pr+0][0] = r[0]; bfr[2*pr+0][1] = r[2];
                bfr[2*pr+1][0] = r[1]; bfr[2*pr+1][1] = r[3];
            }
#pragma unroll
            for (int mf = 0; mf < 2; mf++)
#pragma unroll
                for (int nf = 0; nf < 4; nf++)
                    mma16816(acc[mf][nf], af[mf], bfr[nf]);
        }
        __syncthreads();
    }

    const int erow = row0 + warp_m*32 + (lane >> 2);
    const int ecol = warp_n*32 + (lane & 3)*2;
#pragma unroll
    for (int mf = 0; mf < 2; mf++) {
#pragma unroll
        for (int nf = 0; nf < 4; nf++) {
            __nv_bfloat162* q0 = (__nv_bfloat162*)(C + (size_t)(erow + mf*16    )*128 + ecol + nf*8);
            __nv_bfloat162* q1 = (__nv_bfloat162*)(C + (size_t)(erow + mf*16 + 8)*128 + ecol + nf*8);
            *q0 = __floats2bfloat162_rn(tanhf(acc[mf][nf][0]), tanhf(acc[mf][nf][1]));
            *q1 = __floats2bfloat162_rn(tanhf(acc[mf][nf][2]), tanhf(acc[mf][nf][3]));
        }
    }
}

// ---------------------------------------------------------------------------
// Fat-N GEMM:  C[8192,2048] (fp32, +bias) = A[8192,K] @ Bt[2048,K]^T, K=nk32*32
// ---------------------------------------------------------------------------
__global__ void __launch_bounds__(256) gemm_fatN(
    const __nv_bfloat16* __restrict__ A, int lda,
    const __nv_bfloat16* __restrict__ Bt,
    float* __restrict__ Cm, const float* __restrict__ bias, int nk32)
{
    extern __shared__ char smem2[];
    const uint32_t sbase = smem_u32(smem2);

    const int tid    = threadIdx.x;
    const int lane   = tid & 31;
    const int wid    = tid >> 5;
    const int warp_m = wid & 1;
    const int warp_n = wid >> 1;
    const int row0   = blockIdx.y * 128;
    const int col0   = blockIdx.x * 128;
    const int ldb    = nk32 * 32;

    for (int ch = 0; ch < nk32; ch++) {
        const uint32_t bb = sbase + (uint32_t)ch * 20480u;
#pragma unroll
        for (int s = 0; s < 2; s++) {
            int idx = tid + s*256;
            int row = idx >> 2, quad = idx & 3;
            cp16(bb + (uint32_t)row*80u + (uint32_t)quad*16u,
                 A + (size_t)(row0 + row)*lda + ch*32 + quad*8);
            cp16(bb + 10240u + (uint32_t)row*80u + (uint32_t)quad*16u,
                 Bt + (size_t)(col0 + row)*ldb + ch*32 + quad*8);
        }
    }
    CP_COMMIT();
    CP_WAIT(0);
    __syncthreads();

    float acc[4][4][4];
#pragma unroll
    for (int i = 0; i < 4; i++)
#pragma unroll
        for (int j = 0; j < 4; j++)
#pragma unroll
            for (int q = 0; q < 4; q++) acc[i][j][q] = 0.f;

    const uint32_t lrow  = (uint32_t)(lane & 15);
    const uint32_t khalf = (uint32_t)((lane >> 4) << 3);

    for (int ch = 0; ch < nk32; ch++) {
        const uint32_t aB = sbase + (uint32_t)ch * 20480u;
        const uint32_t bB = aB + 10240u;
#pragma unroll
        for (int k16 = 0; k16 < 32; k16 += 16) {
            const uint32_t kb = ((uint32_t)k16 + khalf) * 2u;
            uint32_t af[4][4], bfr[4][2];
#pragma unroll
            for (int f = 0; f < 4; f++)
                ldsm4(af[f], aB + (uint32_t)(warp_m*64 + f*16 + lrow)*80u + kb);
#pragma unroll
            for (int pr = 0; pr < 2; pr++) {
                uint32_t r[4];
                ldsm4(r, bB + (uint32_t)(warp_n*32 + pr*16 + lrow)*80u + kb);
                bfr[2*pr+0][0] = r[0]; bfr[2*pr+0][1] = r[2];
                bfr[2*pr+1][0] = r[1]; bfr[2*pr+1][1] = r[3];
            }
#pragma unroll
            for (int mf = 0; mf < 4; mf++)
#pragma unroll
                for (int nf = 0; nf < 4; nf++)
                    mma16816(acc[mf][nf], af[mf], bfr[nf]);
        }
    }

    const int erow = row0 + warp_m*64 + (lane >> 2);
    const int ecol = col0 + warp_n*32 + (lane & 3)*2;
#pragma unroll
    for (int mf = 0; mf < 4; mf++) {
#pragma unroll
        for (int nf = 0; nf < 4; nf++) {
            float b0 = 0.f, b1 = 0.f;
            if (bias) { b0 = bias[ecol + nf*8]; b1 = bias[ecol + nf*8 + 1]; }
            float* p0 = Cm + (size_t)(erow + mf*16    )*2048 + ecol + nf*8;
            float* p1 = Cm + (size_t)(erow + mf*16 + 8)*2048 + ecol + nf*8;
            *(float2*)p0 = make_float2(acc[mf][nf][0] + b0, acc[mf][nf][1] + b1);
            *(float2*)p1 = make_float2(acc[mf][nf][2] + b0, acc[mf][nf][3] + b1);
        }
    }
}

// ---------------------------------------------------------------------------
// fp32 -> (hi, lo) bf16 conversion, vectorized by 4.
// ---------------------------------------------------------------------------
__global__ void cvt_hilo(const float* __restrict__ in,
                         __nv_bfloat16* __restrict__ hi,
                         __nv_bfloat16* __restrict__ lo, int n4)
{
    int i = blockIdx.x * blockDim.x + threadIdx.x;
    if (i >= n4) return;
    float4 f = ((const float4*)in)[i];
    __nv_bfloat16 h0 = __float2bfloat16(f.x), h1 = __float2bfloat16(f.y);
    __nv_bfloat16 h2 = __float2bfloat16(f.z), h3 = __float2bfloat16(f.w);
    __nv_bfloat16 l0 = __float2bfloat16(f.x - __bfloat162float(h0));
    __nv_bfloat16 l1 = __float2bfloat16(f.y - __bfloat162float(h1));
    __nv_bfloat16 l2 = __float2bfloat16(f.z - __bfloat162float(h2));
    __nv_bfloat16 l3 = __float2bfloat16(f.w - __bfloat162float(h3));
    uint2 up, lp;
    ((__nv_bfloat16*)&up)[0] = h0; ((__nv_bfloat16*)&up)[1] = h1;
    ((__nv_bfloat16*)&up)[2] = h2; ((__nv_bfloat16*)&up)[3] = h3;
    ((__nv_bfloat16*)&lp)[0] = l0; ((__nv_bfloat16*)&lp)[1] = l1;
    ((__nv_bfloat16*)&lp)[2] = l2; ((__nv_bfloat16*)&lp)[3] = l3;
    ((uint2*)hi)[i] = up;
    ((uint2*)lo)[i] = lp;
}

// Transpose weight fp32[K,N] -> bf16[NPAD,K], rows >= N zero-filled.
__global__ void cvt_wt(const float* __restrict__ in, __nv_bfloat16* __restrict__ out,
                       int K, int N, int NPAD)
{
    int idx = blockIdx.x * blockDim.x + threadIdx.x;
    if (idx >= NPAD * K) return;
    int n = idx / K, k = idx - n * K;
    float v = (n < N) ? in[(size_t)k * N + n] : 0.f;
    out[idx] = __float2bfloat16(v);
}

// ======================== elementwise / scan / LN ==========================
__global__ void xw_kernel(const float* __restrict__ x, const float* __restrict__ mw,
                          const float* __restrict__ shift, const float* __restrict__ maa_w,
                          __nv_bfloat16* __restrict__ xw)
{
    size_t idx = (size_t)blockIdx.x * blockDim.x + threadIdx.x;
    int   c  = (int)(idx & (C_-1));
    size_t bt = idx >> 11;
    int   t  = (int)(bt & (T_-1));
    int   b  = (int)(bt >> 11);
    float xv   = x[idx];
    float prev = t ? x[idx - C_] : shift[b*C_ + c];
    xw[idx] = __float2bfloat16(xv + (prev - xv) * (maa_w[c] + mw[idx]));
}

__global__ void rkv_kernel(const float* __restrict__ x,  const float* __restrict__ shift,
                           const float* __restrict__ mr, const float* __restrict__ mk,
                           const float* __restrict__ mv, const float* __restrict__ mv2,
                           const float* __restrict__ w,
                           const float* __restrict__ maa_r, const float* __restrict__ maa_k,
                           const float* __restrict__ maa_v, const float* __restrict__ maa_v2,
                           const float* __restrict__ t_r,   const float* __restrict__ t_k,
                           float* __restrict__ r, float* __restrict__ k,
                           float* __restrict__ v, float* __restrict__ v2,
                           float* __restrict__ dec)
{
    size_t idx = (size_t)blockIdx.x * blockDim.x + threadIdx.x;
    int   c  = (int)(idx & (C_-1));
    size_t bt = idx >> 11;
    int   t  = (int)(bt & (T_-1));
    int   b  = (int)(bt >> 11);
    float xv   = x[idx];
    float prev = t ? x[idx - C_] : shift[b*C_ + c];
    float dx   = prev - xv;
    float d    = expf(-expf(w[idx]));
    r[idx]   = (xv + dx*(maa_r[c]  + mr[idx]))  * t_r[c];
    k[idx]   = (xv + dx*(maa_k[c]  + mk[idx]))  * t_k[c] * (1.f - d);
    v[idx]   =  xv + dx*(maa_v[c]  + mv[idx]);
    v2[idx]  =  xv + dx*(maa_v2[c] + mv2[idx]);
    dec[idx] = d;
}

// ---------------------------------------------------------------------------
// WKV6 scan, 4-way column split.  Grid (128 bh, 4 slices), 256 threads.
// Thread (q = tid&15, j = tid>>4) owns state rows 4q..4q+3 of column
// slice*16 + j, in registers.  float4 LDS; reduction over q via 4 shfl_xor.
// ---------------------------------------------------------------------------
__global__ void __launch_bounds__(256) wkv_kernel(
    const float* __restrict__ r, const float* __restrict__ k,
    const float* __restrict__ v, const float* __restrict__ d,
    const float* __restrict__ s0, float* __restrict__ y)
{
    const int bh    = blockIdx.x;
    const int slice = blockIdx.y;
    const int b  = bh >> 5;
    const int h  = bh & 31;
    const int tid = threadIdx.x;
    const int q  = tid & 15;
    const int j  = tid >> 4;
    const int jg = slice * 16 + j;

    __shared__ __align__(16) float sbuf[2][4][64];

    float S0a, S1a, S2a, S3a;
    {
        const size_t sb = (size_t)bh * 64 * 64;
        S0a = s0[sb + (size_t)(4*q+0)*64 + jg];
        S1a = s0[sb + (size_t)(4*q+1)*64 + jg];
        S2a = s0[sb + (size_t)(4*q+2)*64 + jg];
        S3a = s0[sb + (size_t)(4*q+3)*64 + jg];
    }

    const int arr = tid >> 6;
    const int li  = tid & 63;
    const float* src = (arr == 0) ? r : (arr == 1) ? k : (arr == 2) ? v : d;

    size_t base = (size_t)b * T_ * C_ + (size_t)h * 64;
    int p = 0;
    for (int t = 0; t < T_; t++) {
        sbuf[p][arr][li] = src[base + li];
        __syncthreads();

        const float  vv = sbuf[p][2][jg];
        const float4 r4 = ((const float4*)sbuf[p][0])[q];
        const float4 k4 = ((const float4*)sbuf[p][1])[q];
        const float4 d4 = ((const float4*)sbuf[p][3])[q];

        float yp = r4.x*S0a + r4.y*S1a + r4.z*S2a + r4.w*S3a;
        S0a = fmaf(d4.x, S0a, k4.x*vv);
        S1a = fmaf(d4.y, S1a, k4.y*vv);
        S2a = fmaf(d4.z, S2a, k4.z*vv);
        S3a = fmaf(d4.w, S3a, k4.w*vv);

        yp += __shfl_xor_sync(0xffffffffu, yp, 1);
        yp += __shfl_xor_sync(0xffffffffu, yp, 2);
        yp += __shfl_xor_sync(0xffffffffu, yp, 4);
        yp += __shfl_xor_sync(0xffffffffu, yp, 8);
        if (q == 0) y[base + jg] = yp;

        base += C_;
        p ^= 1;
    }
}

__global__ void __launch_bounds__(256) ln_kernel(
    const float* __restrict__ y, const float* __restrict__ v2,
    const float* __restrict__ gamma, const float* __restrict__ beta,
    __nv_bfloat16* __restrict__ yh, __nv_bfloat16* __restrict__ yl)
{
    const int row = blockIdx.x;
    const int tid = threadIdx.x;
    __shared__ float buf[C_];
    __shared__ float aux[2][8];

    const size_t base = (size_t)row * C_;
    float s = 0.f, s2 = 0.f;
    for (int c = tid; c < C_; c += 256) {
        float val = y[base + c] + v2[base + c];
        buf[c] = val;
        s += val; s2 += val*val;
    }
#pragma unroll
    for (int o = 16; o; o >>= 1) {
        s  += __shfl_xor_sync(0xffffffffu, s,  o);
        s2 += __shfl_xor_sync(0xffffffffu, s2, o);
    }
    if ((tid & 31) == 0) { aux[0][tid >> 5] = s; aux[1][tid >> 5] = s2; }
    __syncthreads();
    float ts = 0.f, ts2 = 0.f;
#pragma unroll
    for (int wpi = 0; wpi < 8; wpi++) { ts += aux[0][wpi]; ts2 += aux[1][wpi]; }
    const float mu  = ts * (1.f / C_);
    const float var = ts2 * (1.f / C_) - mu*mu;
    const float inv = rsqrtf(var + 1e-5f);
    for (int c = tid; c < C_; c += 256) {
        float o = (buf[c] - mu) * inv * gamma[c] + beta[c];
        __nv_bfloat16 h = __float2bfloat16(o);
        yh[base + c] = h;
        yl[base + c] = __float2bfloat16(o - __bfloat162float(h));
    }
}

// ---------------------------------------------------------------------------
extern "C" void kernel_launch(void* const* d_in, const int* in_sizes, int n_in,
                              void* d_out, int out_size)
{
    const float* x_in    = (const float*)d_in[0];
    const float* shift   = (const float*)d_in[1];
    const float* wkv_s   = (const float*)d_in[2];
    const float* maa_r   = (const float*)d_in[3];
    const float* maa_k   = (const float*)d_in[4];
    const float* maa_v   = (const float*)d_in[5];
    const float* maa_v2  = (const float*)d_in[6];
    const float* maa_w1  = (const float*)d_in[7];
    const float* maa_w2  = (const float*)d_in[8];
    const float* maa_w   = (const float*)d_in[9];
    const float* w_w1    = (const float*)d_in[10];
    const float* w_w2    = (const float*)d_in[11];
    const float* t_decay = (const float*)d_in[12];
    const float* dec_w1  = (const float*)d_in[13];
    const float* dec_w2  = (const float*)d_in[14];
    /* d_in[15] time_faaaa: dead (u = 0 in reference) */
    const float* t_rec   = (const float*)d_in[16];
    const float* t_key   = (const float*)d_in[17];
    const float* val_w   = (const float*)d_in[18];
    const float* out_w   = (const float*)d_in[19];
    const float* gamma   = (const float*)d_in[20];
    const float* beta    = (const float*)d_in[21];
    float* outp = (float*)d_out;

    float* sp = nullptr;
    cudaGetSymbolAddress((void**)&sp, g_scratch);
    __nv_bfloat16* bp = nullptr;
    cudaGetSymbolAddress((void**)&bp, g_bf16);

    float* gx    = sp + OFF_X;
    float* gmixf[4] = {sp + OFF_MIX0, sp + OFF_MIX1, sp + OFF_MIX2, sp + OFF_MIX3};
    float* gmw   = sp + OFF_MW;
    float* gw    = sp + OFF_W;
    float* gr    = sp + OFF_R;
    float* gk    = sp + OFF_K;
    float* gv    = sp + OFF_V;
    float* gv2   = sp + OFF_V2;
    float* gdec  = sp + OFF_DEC;
    float* gy    = sp + OFF_Y;

    __nv_bfloat16* xh   = bp + BF_XH;
    __nv_bfloat16* xl   = bp + BF_XL;
    __nv_bfloat16* yh   = bp + BF_YH;
    __nv_bfloat16* yl   = bp + BF_YL;
    __nv_bfloat16* vwh  = bp + BF_VWH;
    __nv_bfloat16* vwl  = bp + BF_VWL;
    __nv_bfloat16* owh  = bp + BF_OWH;
    __nv_bfloat16* owl  = bp + BF_OWL;
    __nv_bfloat16* gxbf = bp + BF_GXBF;
    __nv_bfloat16* xwbf = bp + BF_XWBF;
    __nv_bfloat16* xxxb = bp + BF_XXX;
    __nv_bfloat16* h32p = bp + BF_H32;
    __nv_bfloat16* h128 = bp + BF_H128;
    __nv_bfloat16* w1t  = bp + BF_W1T;
    __nv_bfloat16* ww1t = bp + BF_WW1T;
    __nv_bfloat16* dw1t = bp + BF_DW1T;
    __nv_bfloat16* w2t  = bp + BF_W2T;
    __nv_bfloat16* ww2t = bp + BF_WW2T;
    __nv_bfloat16* dw2t = bp + BF_DW2T;

    cudaFuncSetAttribute(gemm_mma,  cudaFuncAttributeMaxDynamicSharedMemorySize, GM_SMEM);
    cudaFuncSetAttribute(gemm_fatN, cudaFuncAttributeMaxDynamicSharedMemorySize, 81920);

    const dim3 gBig256(C_/128, MT_/256);       // (16, 32) for 256x128 tiles
    const dim3 gFat(C_/128, MT_/128);          // (16, 64)
    const unsigned ewBlocks = (unsigned)(MTC_ / 256);

    // 0) conversions
    cvt_hilo<<<(unsigned)(MTC_/4/256), 256>>>(x_in,  xh,  xl,  (int)(MTC_/4));
    cvt_hilo<<<(unsigned)(C_*(size_t)C_/4/256), 256>>>(val_w, vwh, vwl, C_*C_/4);
    cvt_hilo<<<(unsigned)(C_*(size_t)C_/4/256), 256>>>(out_w, owh, owl, C_*C_/4);
    cvt_wt<<<1024, 256>>>(maa_w1, w1t,  2048, 128, 128);
    cvt_wt<<<1024, 256>>>(w_w1,   ww1t, 2048,  32, 128);
    cvt_wt<<<1024, 256>>>(dec_w1, dw1t, 2048, 128, 128);
    for (int f = 0; f < 4; f++)
        cvt_wt<<<256, 256>>>(maa_w2 + (size_t)f*32*2048, w2t + (size_t)f*65536, 32, 2048, 2048);
    cvt_wt<<<256, 256>>>(w_w2,   ww2t,  32, 2048, 2048);
    cvt_wt<<<1024, 256>>>(dec_w2, dw2t, 128, 2048, 2048);

    // 1) x = x_in @ value_w^T  (split-bf16)  -> gx fp32 + gxbf bf16
    gemm_mma<<<gBig256, 256, GM_SMEM>>>(xh, xl, vwh, vwl, gx, gxbf);

    // 2) xxx = tanh(x_in @ maa_w1)  -> bf16 [8192,128]
    gemm_skinny<<<MT_/64, 256>>>(xh, w1t, xxxb);

    // 3) mix_f = xxx[:, f*32:] @ maa_w2[f]
    for (int f = 0; f < 4; f++)
        gemm_fatN<<<gFat, 256, 20480>>>(xxxb + f*32, 128, w2t + (size_t)f*65536,
                                        gmixf[f], nullptr, 1);

    // 4) h32 = tanh(x @ w_w1)  (padded to N=128)
    gemm_skinny<<<MT_/64, 256>>>(gxbf, ww1t, h32p);

    // 5) mw = h32 @ w_w2
    gemm_fatN<<<gFat, 256, 20480>>>(h32p, 128, ww2t, gmw, nullptr, 1);

    // 6) xw -> bf16
    xw_kernel<<<ewBlocks,256>>>(gx, gmw, shift, maa_w, xwbf);

    // 7) h128 = tanh(xw @ dec_w1)
    gemm_skinny<<<MT_/64, 256>>>(xwbf, dw1t, h128);

    // 8) w = time_decay + h128 @ dec_w2
    gemm_fatN<<<gFat, 256, 81920>>>(h128, 128, dw2t, gw, t_decay, 4);

    // 9) r,k,v,v2,decay
    rkv_kernel<<<ewBlocks,256>>>(gx, shift, gmixf[0], gmixf[1], gmixf[2], gmixf[3], gw,
        maa_r, maa_k, maa_v, maa_v2, t_rec, t_key,
        gr, gk, gv, gv2, gdec);

    // 10) WKV6 scan (4-way column split)
    wkv_kernel<<<dim3(B_*H_, 4), 256>>>(gr, gk, gv, gdec, wkv_s, gy);

    // 11) LayerNorm(y + v2) -> yh/yl
    ln_kernel<<<MT_,256>>>(gy, gv2, gamma, beta, yh, yl);

    // 12) out = ynorm @ output_w^T  (split-bf16)
    gemm_mma<<<gBig256, 256, GM_SMEM>>>(yh, yl, owh, owl, outp, nullptr);

    (void)in_sizes; (void)n_in; (void)out_size;
}